// round 8
// baseline (speedup 1.0000x reference)
#include <cuda_runtime.h>
#include <cstdint>

#define MAXN 100000
#define MAXE 1000000
#define HDIM 64
#define NLO  50048   // 391 * 128, lo-half row count

// ---------------------------------------------------------------------------
// Static device scratch (no allocation allowed)
// ---------------------------------------------------------------------------
__device__ float g_A1 [2 * MAXN * HDIM];       // layer1 pre-act
__device__ float g_AE1[2 * MAXN * HDIM];       // layer2 pre-act
__device__ float g_B  [2 * MAXN * HDIM];       // layer3 pre-act
__device__ float g_C  [2 * MAXN * HDIM];       // layer4 pre-act
__device__ float g_HW [2 * 4 * MAXN * HDIM];   // GEMM outputs, double-buffered by layer parity
__device__ int   g_cnt   [4 * MAXN];
__device__ int   g_rowptr[4 * (MAXN + 1)];
__device__ int   g_rowofs[4 * MAXN];
__device__ int2  g_cv    [4 * MAXE];
__device__ int   g_part  [4 * 512];

// ---------------------------------------------------------------------------
// SIMT GEMM over a row range: out[r,64] = act(h)[r,DIN] @ W[DIN,64]
// 256 threads, tile 128 rows x 64 cols, 8x4 register tile.
// ---------------------------------------------------------------------------
template <int DIN, bool RELU>
__global__ __launch_bounds__(256) void gemm_kernel(
    float* __restrict__ out, const float* __restrict__ h,
    const float* __restrict__ W, int row_base, int N) {
    extern __shared__ float smem[];
    float* Ws = smem;              // [DIN][64]
    float* hs = smem + DIN * 64;   // [128][DIN]

    const int tid  = threadIdx.x;
    const int row0 = row_base + blockIdx.x * 128;

    for (int i = tid; i < DIN * 16; i += 256)
        reinterpret_cast<float4*>(Ws)[i] = reinterpret_cast<const float4*>(W)[i];

    const int VPR = DIN / 4;
    for (int i = tid; i < 128 * VPR; i += 256) {
        int r = i / VPR, kc = i % VPR;
        int gr = row0 + r;
        float4 v = make_float4(0.f, 0.f, 0.f, 0.f);
        if (gr < N) v = reinterpret_cast<const float4*>(h)[(size_t)gr * VPR + kc];
        if (RELU) {
            v.x = fmaxf(v.x, 0.f); v.y = fmaxf(v.y, 0.f);
            v.z = fmaxf(v.z, 0.f); v.w = fmaxf(v.w, 0.f);
        }
        reinterpret_cast<float4*>(hs)[r * VPR + kc] = v;
    }
    __syncthreads();

    const int tx = tid & 15;
    const int ty = tid >> 4;

    float acc[8][4];
#pragma unroll
    for (int i = 0; i < 8; i++)
#pragma unroll
        for (int j = 0; j < 4; j++) acc[i][j] = 0.f;

#pragma unroll 4
    for (int k = 0; k < DIN; k += 4) {
        float4 b[4];
#pragma unroll
        for (int kk = 0; kk < 4; kk++)
            b[kk] = *reinterpret_cast<float4*>(&Ws[(k + kk) * 64 + tx * 4]);
#pragma unroll
        for (int i = 0; i < 8; i++) {
            float4 a = *reinterpret_cast<float4*>(&hs[(ty * 8 + i) * DIN + k]);
            const float* av = reinterpret_cast<const float*>(&a);
#pragma unroll
            for (int kk = 0; kk < 4; kk++) {
                const float* bv = reinterpret_cast<const float*>(&b[kk]);
                acc[i][0] = fmaf(av[kk], bv[0], acc[i][0]);
                acc[i][1] = fmaf(av[kk], bv[1], acc[i][1]);
                acc[i][2] = fmaf(av[kk], bv[2], acc[i][2]);
                acc[i][3] = fmaf(av[kk], bv[3], acc[i][3]);
            }
        }
    }

#pragma unroll
    for (int i = 0; i < 8; i++) {
        int r = row0 + ty * 8 + i;
        if (r < N) {
            float4 v = make_float4(acc[i][0], acc[i][1], acc[i][2], acc[i][3]);
            reinterpret_cast<float4*>(out + (size_t)r * 64 + tx * 4)[0] = v;
        }
    }
}

// ---------------------------------------------------------------------------
// CSR build kernels
// ---------------------------------------------------------------------------
__global__ void hist_kernel(int* __restrict__ cnt, const int* __restrict__ rows,
                            int E, int N) {
    int i = blockIdx.x * blockDim.x + threadIdx.x;
    if (i >= 4 * E) return;
    int t = i / E;
    atomicAdd(&cnt[t * N + __ldg(rows + i)], 1);
}

__global__ void scan_phase1(const int* __restrict__ cnt, int* __restrict__ part,
                            int N, int nb) {
    int t = blockIdx.y, b = blockIdx.x;
    int i = b * 256 + threadIdx.x;
    int v = (i < N) ? cnt[t * N + i] : 0;
#pragma unroll
    for (int o = 16; o; o >>= 1) v += __shfl_down_sync(0xffffffffu, v, o);
    __shared__ int ws[8];
    if ((threadIdx.x & 31) == 0) ws[threadIdx.x >> 5] = v;
    __syncthreads();
    if (threadIdx.x == 0) {
        int s = 0;
#pragma unroll
        for (int j = 0; j < 8; j++) s += ws[j];
        part[t * nb + b] = s;
    }
}

__global__ void scan_phase2(int* __restrict__ part, int* __restrict__ rowptr,
                            int nb, int N, int E) {
    int t = threadIdx.x;
    if (t >= 4) return;
    int s = 0;
    for (int b = 0; b < nb; b++) {
        int v = part[t * nb + b];
        part[t * nb + b] = s;
        s += v;
    }
    rowptr[t * (N + 1) + N] = E;
}

__global__ void scan_phase3(const int* __restrict__ cnt, const int* __restrict__ part,
                            int* __restrict__ rowptr, int* __restrict__ rowofs,
                            int N, int nb) {
    int t = blockIdx.y, b = blockIdx.x;
    int i = b * 256 + threadIdx.x;
    int v = (i < N) ? cnt[t * N + i] : 0;
    __shared__ int sm[256];
    sm[threadIdx.x] = v;
    __syncthreads();
#pragma unroll
    for (int o = 1; o < 256; o <<= 1) {
        int x = (threadIdx.x >= o) ? sm[threadIdx.x - o] : 0;
        __syncthreads();
        sm[threadIdx.x] += x;
        __syncthreads();
    }
    if (i < N) {
        int excl = sm[threadIdx.x] - v + part[t * nb + b];
        rowptr[t * (N + 1) + i] = excl;
        rowofs[t * N + i] = excl;
    }
}

__global__ void fill_kernel(int2* __restrict__ cv, int* __restrict__ rowofs,
                            const int* __restrict__ rows, const int* __restrict__ cols,
                            const float* __restrict__ vals, int E, int N) {
    int i = blockIdx.x * blockDim.x + threadIdx.x;
    if (i >= 4 * E) return;
    int t = i / E;
    int r = __ldg(rows + i);
    int pos = atomicAdd(&rowofs[t * N + r], 1);
    cv[(size_t)t * E + pos] = make_int2(__ldg(cols + i), __float_as_int(__ldg(vals + i)));
}

// ---------------------------------------------------------------------------
// CSR aggregation over a row range, two edge types fused
// ---------------------------------------------------------------------------
__device__ __forceinline__ void fma4(float4& acc, float v, const float4& x) {
    acc.x = fmaf(v, x.x, acc.x);
    acc.y = fmaf(v, x.y, acc.y);
    acc.z = fmaf(v, x.z, acc.z);
    acc.w = fmaf(v, x.w, acc.w);
}

__device__ __forceinline__ void agg_one(float4& acc, const float4* __restrict__ hw,
                                        const int* __restrict__ rp,
                                        const int2* __restrict__ cv, int r, int c) {
    int b = __ldg(rp + r);
    int e = __ldg(rp + r + 1);
    while (b + 2 <= e) {
        int2 p0 = __ldg(cv + b);
        int2 p1 = __ldg(cv + b + 1);
        float4 x0 = __ldg(hw + (size_t)p0.x * 16 + c);
        float4 x1 = __ldg(hw + (size_t)p1.x * 16 + c);
        fma4(acc, __int_as_float(p0.y), x0);
        fma4(acc, __int_as_float(p1.y), x1);
        b += 2;
    }
    if (b < e) {
        int2 p = __ldg(cv + b);
        float4 x = __ldg(hw + (size_t)p.x * 16 + c);
        fma4(acc, __int_as_float(p.y), x);
    }
}

__global__ __launch_bounds__(256) void agg2_kernel(
    float4* __restrict__ out,
    const float4* __restrict__ hw0, const float4* __restrict__ hw1,
    const int* __restrict__ rp0, const int2* __restrict__ cv0,
    const int* __restrict__ rp1, const int2* __restrict__ cv1, int r0, int rn) {
    int gid = blockIdx.x * blockDim.x + threadIdx.x;
    if (gid >= rn * 16) return;
    int r = r0 + (gid >> 4), c = gid & 15;
    float4 acc = make_float4(0.f, 0.f, 0.f, 0.f);
    agg_one(acc, hw0, rp0, cv0, r, c);
    agg_one(acc, hw1, rp1, cv1, r, c);
    out[(size_t)r * 16 + c] = acc;
}

// Layer-5 agg fused with the final attention-concat epilogue.
// out row r gets: [0:64) relu(A1)*a0 | [64:128) relu(AE1)*a1 | [128:192) (p+relu(A1))*a2
__global__ __launch_bounds__(256) void agg2_final_kernel(
    float* __restrict__ out,
    const float4* __restrict__ A1, const float4* __restrict__ AE1,
    const float4* __restrict__ hw0, const float4* __restrict__ hw1,
    const int* __restrict__ rp0, const int2* __restrict__ cv0,
    const int* __restrict__ rp1, const int2* __restrict__ cv1,
    const float* __restrict__ att, int r0, int rn) {
    int gid = blockIdx.x * blockDim.x + threadIdx.x;
    if (gid >= rn * 16) return;
    int r = r0 + (gid >> 4), c = gid & 15;

    float4 p = make_float4(0.f, 0.f, 0.f, 0.f);
    agg_one(p, hw0, rp0, cv0, r, c);
    agg_one(p, hw1, rp1, cv1, r, c);

    float a0 = __ldg(att + 0), a1 = __ldg(att + 1), a2 = __ldg(att + 2);

    float4 x1 = A1[(size_t)r * 16 + c];
    x1.x = fmaxf(x1.x, 0.f); x1.y = fmaxf(x1.y, 0.f);
    x1.z = fmaxf(x1.z, 0.f); x1.w = fmaxf(x1.w, 0.f);

    float4 xe = AE1[(size_t)r * 16 + c];
    xe.x = fmaxf(xe.x, 0.f); xe.y = fmaxf(xe.y, 0.f);
    xe.z = fmaxf(xe.z, 0.f); xe.w = fmaxf(xe.w, 0.f);

    float4 emb = make_float4(p.x + x1.x, p.y + x1.y, p.z + x1.z, p.w + x1.w);

    float* o = out + (size_t)r * 192 + (size_t)c * 4;
    reinterpret_cast<float4*>(o + 0)[0]   = make_float4(x1.x * a0, x1.y * a0, x1.z * a0, x1.w * a0);
    reinterpret_cast<float4*>(o + 64)[0]  = make_float4(xe.x * a1, xe.y * a1, xe.z * a1, xe.w * a1);
    reinterpret_cast<float4*>(o + 128)[0] = make_float4(emb.x * a2, emb.y * a2, emb.z * a2, emb.w * a2);
}

// ---------------------------------------------------------------------------
// Host launcher — SG (all GEMMs) + SA (CSR + all aggs), row-halved pipeline.
// ---------------------------------------------------------------------------
struct PipeCtx {
    cudaStream_t sg, sa;
    cudaEvent_t efork;
    cudaEvent_t e01[5], e23[5];                      // GEMM groups done (on SG)
    cudaEvent_t eAlo0[5], eAhi0[5], eAlo1[5], eAhi1[5];  // agg halves done (on SA)
    PipeCtx() {
        cudaStreamCreateWithFlags(&sg, cudaStreamNonBlocking);
        cudaStreamCreateWithFlags(&sa, cudaStreamNonBlocking);
        cudaEventCreateWithFlags(&efork, cudaEventDisableTiming);
        for (int i = 0; i < 5; i++) {
            cudaEventCreateWithFlags(&e01[i], cudaEventDisableTiming);
            cudaEventCreateWithFlags(&e23[i], cudaEventDisableTiming);
            cudaEventCreateWithFlags(&eAlo0[i], cudaEventDisableTiming);
            cudaEventCreateWithFlags(&eAhi0[i], cudaEventDisableTiming);
            cudaEventCreateWithFlags(&eAlo1[i], cudaEventDisableTiming);
            cudaEventCreateWithFlags(&eAhi1[i], cudaEventDisableTiming);
        }
    }
};
static PipeCtx& pipe_ctx() { static PipeCtx c; return c; }

extern "C" void kernel_launch(void* const* d_in, const int* in_sizes, int n_in,
                              void* d_out, int out_size) {
    const float* feat0 = (const float*)d_in[0];
    const float* feat1 = (const float*)d_in[1];
    const int*   rows  = (const int*)  d_in[2];
    const int*   cols  = (const int*)  d_in[3];
    const float* vals  = (const float*)d_in[4];
    const float* Wl[5] = {(const float*)d_in[5], (const float*)d_in[6], (const float*)d_in[7],
                          (const float*)d_in[8], (const float*)d_in[9]};
    const float* att   = (const float*)d_in[10];
    float* out = (float*)d_out;

    const int N = in_sizes[0] / 128;   // 100000
    const int E = in_sizes[2] / 4;     // 1000000

    float *A1, *AE1, *B, *C, *HW;
    int *cnt, *rowptr, *rowofs, *part;
    int2* cv;
    cudaGetSymbolAddress((void**)&A1,     g_A1);
    cudaGetSymbolAddress((void**)&AE1,    g_AE1);
    cudaGetSymbolAddress((void**)&B,      g_B);
    cudaGetSymbolAddress((void**)&C,      g_C);
    cudaGetSymbolAddress((void**)&HW,     g_HW);
    cudaGetSymbolAddress((void**)&cnt,    g_cnt);
    cudaGetSymbolAddress((void**)&rowptr, g_rowptr);
    cudaGetSymbolAddress((void**)&rowofs, g_rowofs);
    cudaGetSymbolAddress((void**)&cv,     g_cv);
    cudaGetSymbolAddress((void**)&part,   g_part);

    const int SMEM64  = (64 * 64 + 128 * 64) * 4;    // 48 KB
    const int SMEM128 = (128 * 64 + 128 * 128) * 4;  // 96 KB
    cudaFuncSetAttribute(gemm_kernel<128, false>, cudaFuncAttributeMaxDynamicSharedMemorySize, SMEM128);
    cudaFuncSetAttribute(gemm_kernel<64, true>,   cudaFuncAttributeMaxDynamicSharedMemorySize, SMEM64);

    PipeCtx& px = pipe_ctx();
    cudaStream_t S0 = 0, SG = px.sg, SA = px.sa;

    const int NHI = N - NLO;
    const int gb_half = (NLO + 127) / 128;        // 391 blocks, covers both halves
    const int ab_lo = (NLO * 16 + 255) / 256;
    const int ab_hi = (NHI * 16 + 255) / 256;
    const size_t half = (size_t)N * 64;

    auto rp  = [&](int t) { return rowptr + (size_t)t * (N + 1); };
    auto cvp = [&](int t) { return cv + (size_t)t * E; };
    auto hw  = [&](int l, int t) { return HW + ((size_t)(l & 1) * 4 + t) * half; };

    // ---- fork ----
    cudaEventRecord(px.efork, S0);
    cudaStreamWaitEvent(SG, px.efork, 0);
    cudaStreamWaitEvent(SA, px.efork, 0);

    // ---- CSR build on SA (overlaps layer-1 GEMMs on SG) ----
    const int nb = (N + 255) / 256;
    cudaMemsetAsync(cnt, 0, (size_t)4 * N * sizeof(int), SA);
    {
        int blocks = (4 * E + 255) / 256;
        hist_kernel<<<blocks, 256, 0, SA>>>(cnt, rows, E, N);
        scan_phase1<<<dim3(nb, 4), 256, 0, SA>>>(cnt, part, N, nb);
        scan_phase2<<<1, 32, 0, SA>>>(part, rowptr, nb, N, E);
        scan_phase3<<<dim3(nb, 4), 256, 0, SA>>>(cnt, part, rowptr, rowofs, N, nb);
        fill_kernel<<<blocks, 256, 0, SA>>>(cv, rowofs, rows, cols, vals, E, N);
    }

    auto gemm = [&](int l, int t, const float* src, int din, int row_base) {
        const float* Wt = Wl[l] + (size_t)t * din * 64;
        if (din == 128)
            gemm_kernel<128, false><<<gb_half, 256, SMEM128, SG>>>(hw(l, t), src, Wt, row_base, N);
        else
            gemm_kernel<64, true><<<gb_half, 256, SMEM64, SG>>>(hw(l, t), src, Wt, row_base, N);
    };

    // Per layer: SG order prioritizes releasing e01 (A01's inputs) early.
    // Waits are monotone in SA's event order: eAlo0 < eAhi0 < eAlo1 < eAhi1.
    for (int l = 0; l < 5; l++) {
        const float* p0;
        const float* p1;
        int din = (l == 0) ? 128 : 64;
        if (l == 0)      { p0 = feat0; p1 = feat1; }
        else {
            const float* src = (l == 1) ? A1 : (l == 2) ? AE1 : (l == 3) ? B : C;
            p0 = src; p1 = src + half;
        }

        // ----- SG: 8 GEMM halves -----
        if (l > 0) cudaStreamWaitEvent(SG, px.eAlo0[l - 1], 0);
        gemm(l, 0, p0, din, 0);          // G0_lo
        if (l > 0) cudaStreamWaitEvent(SG, px.eAhi0[l - 1], 0);
        gemm(l, 0, p0, din, NLO);        // G0_hi
        if (l > 0) cudaStreamWaitEvent(SG, px.eAlo1[l - 1], 0);
        gemm(l, 1, p1, din, 0);          // G1_lo
        if (l > 0) cudaStreamWaitEvent(SG, px.eAhi1[l - 1], 0);
        gemm(l, 1, p1, din, NLO);        // G1_hi
        cudaEventRecord(px.e01[l], SG);
        gemm(l, 2, p0, din, 0);          // G2_lo  (deps already waited)
        gemm(l, 2, p0, din, NLO);        // G2_hi
        gemm(l, 3, p1, din, 0);          // G3_lo
        gemm(l, 3, p1, din, NLO);        // G3_hi
        cudaEventRecord(px.e23[l], SG);

        // ----- SA: 4 agg halves (serial; lo halves first) -----
        float* dst = (l == 0) ? A1 : (l == 1) ? AE1 : (l == 2) ? B : (l == 3) ? C : nullptr;
        cudaStreamWaitEvent(SA, px.e01[l], 0);
        if (l < 4) {
            agg2_kernel<<<ab_lo, 256, 0, SA>>>((float4*)dst,
                (const float4*)hw(l, 0), (const float4*)hw(l, 1),
                rp(0), cvp(0), rp(1), cvp(1), 0, NLO);
            cudaEventRecord(px.eAlo0[l], SA);
            agg2_kernel<<<ab_hi, 256, 0, SA>>>((float4*)dst,
                (const float4*)hw(l, 0), (const float4*)hw(l, 1),
                rp(0), cvp(0), rp(1), cvp(1), NLO, NHI);
            cudaEventRecord(px.eAhi0[l], SA);
            cudaStreamWaitEvent(SA, px.e23[l], 0);
            agg2_kernel<<<ab_lo, 256, 0, SA>>>((float4*)(dst + half),
                (const float4*)hw(l, 2), (const float4*)hw(l, 3),
                rp(2), cvp(2), rp(3), cvp(3), 0, NLO);
            cudaEventRecord(px.eAlo1[l], SA);
            agg2_kernel<<<ab_hi, 256, 0, SA>>>((float4*)(dst + half),
                (const float4*)hw(l, 2), (const float4*)hw(l, 3),
                rp(2), cvp(2), rp(3), cvp(3), NLO, NHI);
            cudaEventRecord(px.eAhi1[l], SA);
        } else {
            // layer 5: fused agg + final concat, chain 0 -> out[s=0], chain 1 -> out[s=1]
            agg2_final_kernel<<<ab_lo, 256, 0, SA>>>(out,
                (const float4*)A1, (const float4*)AE1,
                (const float4*)hw(l, 0), (const float4*)hw(l, 1),
                rp(0), cvp(0), rp(1), cvp(1), att, 0, NLO);
            agg2_final_kernel<<<ab_hi, 256, 0, SA>>>(out,
                (const float4*)A1, (const float4*)AE1,
                (const float4*)hw(l, 0), (const float4*)hw(l, 1),
                rp(0), cvp(0), rp(1), cvp(1), att, NLO, NHI);
            cudaStreamWaitEvent(SA, px.e23[l], 0);
            agg2_final_kernel<<<ab_lo, 256, 0, SA>>>(out + (size_t)N * 192,
                (const float4*)(A1 + half), (const float4*)(AE1 + half),
                (const float4*)hw(l, 2), (const float4*)hw(l, 3),
                rp(2), cvp(2), rp(3), cvp(3), att, 0, NLO);
            agg2_final_kernel<<<ab_hi, 256, 0, SA>>>(out + (size_t)N * 192,
                (const float4*)(A1 + half), (const float4*)(AE1 + half),
                rp(2) == nullptr ? nullptr : (const float4*)hw(l, 2), (const float4*)hw(l, 3),
                rp(2), cvp(2), rp(3), cvp(3), att, NLO, NHI);
            cudaEventRecord(px.eAhi1[l], SA);
        }
    }

    // ---- join back to capture-origin stream ----
    cudaStreamWaitEvent(S0, px.eAhi1[4], 0);
}

// round 9
// speedup vs baseline: 1.1102x; 1.1102x over previous
#include <cuda_runtime.h>
#include <cstdint>

#define MAXN 100000
#define MAXE 1000000
#define HDIM 64

// ---------------------------------------------------------------------------
// Static device scratch (no allocation allowed)
// ---------------------------------------------------------------------------
__device__ float g_A1 [2 * MAXN * HDIM];   // layer1 pre-act (h1 = relu(A1); residual)
__device__ float g_AE1[2 * MAXN * HDIM];   // layer2 pre-act (e1 = relu(AE1))
__device__ float g_B  [2 * MAXN * HDIM];   // layer3 pre-act
__device__ float g_C  [2 * MAXN * HDIM];   // layer4 pre-act
__device__ float g_HW [4 * MAXN * HDIM];   // 4 GEMM outputs (single set — L2 residency!)
__device__ int   g_cnt   [4 * MAXN];
__device__ int   g_rowptr[4 * (MAXN + 1)];
__device__ int   g_rowofs[4 * MAXN];
__device__ int2  g_cv    [4 * MAXE];
__device__ int   g_part  [4 * 512];

// ---------------------------------------------------------------------------
// Packed fp32x2 FMA helpers (sm_100+ PTX; compiles to FFMA2)
// ---------------------------------------------------------------------------
__device__ __forceinline__ unsigned long long pack2(float x) {
    unsigned long long r;
    asm("mov.b64 %0, {%1, %1};" : "=l"(r) : "f"(x));
    return r;
}
__device__ __forceinline__ void ffma2(unsigned long long& d, unsigned long long a,
                                      unsigned long long b) {
    asm("fma.rn.f32x2 %0, %1, %2, %3;" : "=l"(d) : "l"(a), "l"(b), "l"(d));
}
__device__ __forceinline__ void unpack2(unsigned long long v, float& lo, float& hi) {
    asm("mov.b64 {%0, %1}, %2;" : "=f"(lo), "=f"(hi) : "l"(v));
}

// ---------------------------------------------------------------------------
// SIMT GEMM (FFMA2): out[N,64] = act(h)[N,DIN] @ W[DIN,64]
// 256 threads, tile 128 rows x 64 cols, 8x4 register tile (as 8x2 f32x2).
// ---------------------------------------------------------------------------
template <int DIN, bool RELU>
__global__ __launch_bounds__(256) void gemm_kernel(
    float* __restrict__ out, const float* __restrict__ h,
    const float* __restrict__ W, int N) {
    extern __shared__ float smem[];
    float* Ws = smem;              // [DIN][64]
    float* hs = smem + DIN * 64;   // [128][DIN]

    const int tid  = threadIdx.x;
    const int row0 = blockIdx.x * 128;

    for (int i = tid; i < DIN * 16; i += 256)
        reinterpret_cast<float4*>(Ws)[i] = reinterpret_cast<const float4*>(W)[i];

    const int VPR = DIN / 4;
    for (int i = tid; i < 128 * VPR; i += 256) {
        int r = i / VPR, kc = i % VPR;
        int gr = row0 + r;
        float4 v = make_float4(0.f, 0.f, 0.f, 0.f);
        if (gr < N) v = reinterpret_cast<const float4*>(h)[(size_t)gr * VPR + kc];
        if (RELU) {
            v.x = fmaxf(v.x, 0.f); v.y = fmaxf(v.y, 0.f);
            v.z = fmaxf(v.z, 0.f); v.w = fmaxf(v.w, 0.f);
        }
        reinterpret_cast<float4*>(hs)[r * VPR + kc] = v;
    }
    __syncthreads();

    const int tx = tid & 15;   // col group: cols 4*tx..4*tx+3
    const int ty = tid >> 4;   // row group: rows 8*ty..8*ty+7

    unsigned long long acc[8][2];
#pragma unroll
    for (int i = 0; i < 8; i++) { acc[i][0] = 0ull; acc[i][1] = 0ull; }

#pragma unroll 4
    for (int k = 0; k < DIN; k += 4) {
        unsigned long long b2[4][2];
#pragma unroll
        for (int kk = 0; kk < 4; kk++) {
            double2 bd = *reinterpret_cast<double2*>(&Ws[(k + kk) * 64 + tx * 4]);
            b2[kk][0] = __double_as_longlong(bd.x);
            b2[kk][1] = __double_as_longlong(bd.y);
        }
#pragma unroll
        for (int i = 0; i < 8; i++) {
            float4 a = *reinterpret_cast<float4*>(&hs[(ty * 8 + i) * DIN + k]);
            const float* av = reinterpret_cast<const float*>(&a);
#pragma unroll
            for (int kk = 0; kk < 4; kk++) {
                unsigned long long aa = pack2(av[kk]);
                ffma2(acc[i][0], aa, b2[kk][0]);
                ffma2(acc[i][1], aa, b2[kk][1]);
            }
        }
    }

#pragma unroll
    for (int i = 0; i < 8; i++) {
        int r = row0 + ty * 8 + i;
        if (r < N) {
            float4 v;
            unpack2(acc[i][0], v.x, v.y);
            unpack2(acc[i][1], v.z, v.w);
            reinterpret_cast<float4*>(out + (size_t)r * 64 + tx * 4)[0] = v;
        }
    }
}

// ---------------------------------------------------------------------------
// CSR build kernels
// ---------------------------------------------------------------------------
__global__ void hist_kernel(int* __restrict__ cnt, const int* __restrict__ rows,
                            int E, int N) {
    int i = blockIdx.x * blockDim.x + threadIdx.x;
    if (i >= 4 * E) return;
    int t = i / E;
    atomicAdd(&cnt[t * N + __ldg(rows + i)], 1);
}

__global__ void scan_phase1(const int* __restrict__ cnt, int* __restrict__ part,
                            int N, int nb) {
    int t = blockIdx.y, b = blockIdx.x;
    int i = b * 256 + threadIdx.x;
    int v = (i < N) ? cnt[t * N + i] : 0;
#pragma unroll
    for (int o = 16; o; o >>= 1) v += __shfl_down_sync(0xffffffffu, v, o);
    __shared__ int ws[8];
    if ((threadIdx.x & 31) == 0) ws[threadIdx.x >> 5] = v;
    __syncthreads();
    if (threadIdx.x == 0) {
        int s = 0;
#pragma unroll
        for (int j = 0; j < 8; j++) s += ws[j];
        part[t * nb + b] = s;
    }
}

__global__ void scan_phase2(int* __restrict__ part, int* __restrict__ rowptr,
                            int nb, int N, int E) {
    int t = threadIdx.x;
    if (t >= 4) return;
    int s = 0;
    for (int b = 0; b < nb; b++) {
        int v = part[t * nb + b];
        part[t * nb + b] = s;
        s += v;
    }
    rowptr[t * (N + 1) + N] = E;
}

__global__ void scan_phase3(const int* __restrict__ cnt, const int* __restrict__ part,
                            int* __restrict__ rowptr, int* __restrict__ rowofs,
                            int N, int nb) {
    int t = blockIdx.y, b = blockIdx.x;
    int i = b * 256 + threadIdx.x;
    int v = (i < N) ? cnt[t * N + i] : 0;
    __shared__ int sm[256];
    sm[threadIdx.x] = v;
    __syncthreads();
#pragma unroll
    for (int o = 1; o < 256; o <<= 1) {
        int x = (threadIdx.x >= o) ? sm[threadIdx.x - o] : 0;
        __syncthreads();
        sm[threadIdx.x] += x;
        __syncthreads();
    }
    if (i < N) {
        int excl = sm[threadIdx.x] - v + part[t * nb + b];
        rowptr[t * (N + 1) + i] = excl;
        rowofs[t * N + i] = excl;
    }
}

__global__ void fill_kernel(int2* __restrict__ cv, int* __restrict__ rowofs,
                            const int* __restrict__ rows, const int* __restrict__ cols,
                            const float* __restrict__ vals, int E, int N) {
    int i = blockIdx.x * blockDim.x + threadIdx.x;
    if (i >= 4 * E) return;
    int t = i / E;
    int r = __ldg(rows + i);
    int pos = atomicAdd(&rowofs[t * N + r], 1);
    cv[(size_t)t * E + pos] = make_int2(__ldg(cols + i), __float_as_int(__ldg(vals + i)));
}

// ---------------------------------------------------------------------------
// CSR aggregation, two edge types fused per output row (written once)
// ---------------------------------------------------------------------------
__device__ __forceinline__ void fma4(float4& acc, float v, const float4& x) {
    acc.x = fmaf(v, x.x, acc.x);
    acc.y = fmaf(v, x.y, acc.y);
    acc.z = fmaf(v, x.z, acc.z);
    acc.w = fmaf(v, x.w, acc.w);
}

__device__ __forceinline__ void agg_one(float4& acc, const float4* __restrict__ hw,
                                        const int* __restrict__ rp,
                                        const int2* __restrict__ cv, int r, int c) {
    int b = __ldg(rp + r);
    int e = __ldg(rp + r + 1);
    while (b + 2 <= e) {
        int2 p0 = __ldg(cv + b);
        int2 p1 = __ldg(cv + b + 1);
        float4 x0 = __ldg(hw + (size_t)p0.x * 16 + c);
        float4 x1 = __ldg(hw + (size_t)p1.x * 16 + c);
        fma4(acc, __int_as_float(p0.y), x0);
        fma4(acc, __int_as_float(p1.y), x1);
        b += 2;
    }
    if (b < e) {
        int2 p = __ldg(cv + b);
        float4 x = __ldg(hw + (size_t)p.x * 16 + c);
        fma4(acc, __int_as_float(p.y), x);
    }
}

__global__ __launch_bounds__(256) void agg2_kernel(
    float4* __restrict__ out,
    const float4* __restrict__ hw0, const float4* __restrict__ hw1,
    const int* __restrict__ rp0, const int2* __restrict__ cv0,
    const int* __restrict__ rp1, const int2* __restrict__ cv1, int N) {
    int gid = blockIdx.x * blockDim.x + threadIdx.x;
    int r = gid >> 4, c = gid & 15;
    if (r >= N) return;
    float4 acc = make_float4(0.f, 0.f, 0.f, 0.f);
    agg_one(acc, hw0, rp0, cv0, r, c);
    agg_one(acc, hw1, rp1, cv1, r, c);
    out[(size_t)r * 16 + c] = acc;
}

// Layer-5 agg fused with the final attention-concat epilogue (one node class s).
// out row r: [0:64) relu(A1)*a0 | [64:128) relu(AE1)*a1 | [128:192) (p+relu(A1))*a2
__global__ __launch_bounds__(256) void agg2_final_kernel(
    float* __restrict__ out,
    const float4* __restrict__ A1, const float4* __restrict__ AE1,
    const float4* __restrict__ hw0, const float4* __restrict__ hw1,
    const int* __restrict__ rp0, const int2* __restrict__ cv0,
    const int* __restrict__ rp1, const int2* __restrict__ cv1,
    const float* __restrict__ att, int N) {
    int gid = blockIdx.x * blockDim.x + threadIdx.x;
    if (gid >= N * 16) return;
    int r = gid >> 4, c = gid & 15;

    float4 p = make_float4(0.f, 0.f, 0.f, 0.f);
    agg_one(p, hw0, rp0, cv0, r, c);
    agg_one(p, hw1, rp1, cv1, r, c);

    float a0 = __ldg(att + 0), a1 = __ldg(att + 1), a2 = __ldg(att + 2);

    float4 x1 = A1[(size_t)r * 16 + c];
    x1.x = fmaxf(x1.x, 0.f); x1.y = fmaxf(x1.y, 0.f);
    x1.z = fmaxf(x1.z, 0.f); x1.w = fmaxf(x1.w, 0.f);

    float4 xe = AE1[(size_t)r * 16 + c];
    xe.x = fmaxf(xe.x, 0.f); xe.y = fmaxf(xe.y, 0.f);
    xe.z = fmaxf(xe.z, 0.f); xe.w = fmaxf(xe.w, 0.f);

    float4 emb = make_float4(p.x + x1.x, p.y + x1.y, p.z + x1.z, p.w + x1.w);

    float* o = out + (size_t)r * 192 + (size_t)c * 4;
    reinterpret_cast<float4*>(o + 0)[0]   = make_float4(x1.x * a0, x1.y * a0, x1.z * a0, x1.w * a0);
    reinterpret_cast<float4*>(o + 64)[0]  = make_float4(xe.x * a1, xe.y * a1, xe.z * a1, xe.w * a1);
    reinterpret_cast<float4*>(o + 128)[0] = make_float4(emb.x * a2, emb.y * a2, emb.z * a2, emb.w * a2);
}

// ---------------------------------------------------------------------------
// Host launcher — SG (all GEMMs) + SA (CSR + all aggs) pipeline, single HW set.
// ---------------------------------------------------------------------------
struct PipeCtx {
    cudaStream_t sg, sa;
    cudaEvent_t efork;
    cudaEvent_t eG01[5], eG23[5];  // GEMM pairs done (SG)
    cudaEvent_t eA01[5], eA23[5];  // aggs done (SA)
    PipeCtx() {
        cudaStreamCreateWithFlags(&sg, cudaStreamNonBlocking);
        cudaStreamCreateWithFlags(&sa, cudaStreamNonBlocking);
        cudaEventCreateWithFlags(&efork, cudaEventDisableTiming);
        for (int i = 0; i < 5; i++) {
            cudaEventCreateWithFlags(&eG01[i], cudaEventDisableTiming);
            cudaEventCreateWithFlags(&eG23[i], cudaEventDisableTiming);
            cudaEventCreateWithFlags(&eA01[i], cudaEventDisableTiming);
            cudaEventCreateWithFlags(&eA23[i], cudaEventDisableTiming);
        }
    }
};
static PipeCtx& pipe_ctx() { static PipeCtx c; return c; }

extern "C" void kernel_launch(void* const* d_in, const int* in_sizes, int n_in,
                              void* d_out, int out_size) {
    const float* feat0 = (const float*)d_in[0];
    const float* feat1 = (const float*)d_in[1];
    const int*   rows  = (const int*)  d_in[2];
    const int*   cols  = (const int*)  d_in[3];
    const float* vals  = (const float*)d_in[4];
    const float* Wl[5] = {(const float*)d_in[5], (const float*)d_in[6], (const float*)d_in[7],
                          (const float*)d_in[8], (const float*)d_in[9]};
    const float* att   = (const float*)d_in[10];
    float* out = (float*)d_out;

    const int N = in_sizes[0] / 128;   // 100000
    const int E = in_sizes[2] / 4;     // 1000000

    float *A1, *AE1, *B, *C, *HW;
    int *cnt, *rowptr, *rowofs, *part;
    int2* cv;
    cudaGetSymbolAddress((void**)&A1,     g_A1);
    cudaGetSymbolAddress((void**)&AE1,    g_AE1);
    cudaGetSymbolAddress((void**)&B,      g_B);
    cudaGetSymbolAddress((void**)&C,      g_C);
    cudaGetSymbolAddress((void**)&HW,     g_HW);
    cudaGetSymbolAddress((void**)&cnt,    g_cnt);
    cudaGetSymbolAddress((void**)&rowptr, g_rowptr);
    cudaGetSymbolAddress((void**)&rowofs, g_rowofs);
    cudaGetSymbolAddress((void**)&cv,     g_cv);
    cudaGetSymbolAddress((void**)&part,   g_part);

    const int SMEM64  = (64 * 64 + 128 * 64) * 4;    // 48 KB
    const int SMEM128 = (128 * 64 + 128 * 128) * 4;  // 96 KB
    cudaFuncSetAttribute(gemm_kernel<128, false>, cudaFuncAttributeMaxDynamicSharedMemorySize, SMEM128);
    cudaFuncSetAttribute(gemm_kernel<64, true>,   cudaFuncAttributeMaxDynamicSharedMemorySize, SMEM64);

    PipeCtx& px = pipe_ctx();
    cudaStream_t S0 = 0, SG = px.sg, SA = px.sa;

    const int gblocks = (N + 127) / 128;
    const int ablocks = (N * 16 + 255) / 256;
    const size_t half = (size_t)N * 64;

    auto rp  = [&](int t) { return rowptr + (size_t)t * (N + 1); };
    auto cvp = [&](int t) { return cv + (size_t)t * E; };
    auto hw  = [&](int t) { return HW + (size_t)t * half; };

    // ---- fork ----
    cudaEventRecord(px.efork, S0);
    cudaStreamWaitEvent(SG, px.efork, 0);
    cudaStreamWaitEvent(SA, px.efork, 0);

    // ---- CSR build on SA (overlaps layer-0 GEMMs on SG) ----
    const int nb = (N + 255) / 256;
    cudaMemsetAsync(cnt, 0, (size_t)4 * N * sizeof(int), SA);
    {
        int blocks = (4 * E + 255) / 256;
        hist_kernel<<<blocks, 256, 0, SA>>>(cnt, rows, E, N);
        scan_phase1<<<dim3(nb, 4), 256, 0, SA>>>(cnt, part, N, nb);
        scan_phase2<<<1, 32, 0, SA>>>(part, rowptr, nb, N, E);
        scan_phase3<<<dim3(nb, 4), 256, 0, SA>>>(cnt, part, rowptr, rowofs, N, nb);
        fill_kernel<<<blocks, 256, 0, SA>>>(cv, rowofs, rows, cols, vals, E, N);
    }

    auto gemm = [&](int l, int t, const float* src, int din) {
        const float* Wt = Wl[l] + (size_t)t * din * 64;
        if (din == 128)
            gemm_kernel<128, false><<<gblocks, 256, SMEM128, SG>>>(hw(t), src, Wt, N);
        else
            gemm_kernel<64, true><<<gblocks, 256, SMEM64, SG>>>(hw(t), src, Wt, N);
    };

    float* dsts[4] = {A1, AE1, B, C};
    for (int l = 0; l < 5; l++) {
        const float* p0;
        const float* p1;
        int din = (l == 0) ? 128 : 64;
        if (l == 0) { p0 = feat0; p1 = feat1; }
        else        { p0 = dsts[l - 1]; p1 = dsts[l - 1] + half; }

        // ----- SG: G0 [needs A01(l-1)], G1 [needs A23(l-1)], G2, G3 -----
        // In-order stream: G2/G3 inherit both waits, covering WAR on hw2/hw3.
        if (l > 0) cudaStreamWaitEvent(SG, px.eA01[l - 1], 0);
        gemm(l, 0, p0, din);
        if (l > 0) cudaStreamWaitEvent(SG, px.eA23[l - 1], 0);
        gemm(l, 1, p1, din);
        cudaEventRecord(px.eG01[l], SG);
        gemm(l, 2, p0, din);
        gemm(l, 3, p1, din);
        cudaEventRecord(px.eG23[l], SG);

        // ----- SA: A01 then A23 -----
        cudaStreamWaitEvent(SA, px.eG01[l], 0);
        if (l < 4) {
            float* dst = dsts[l];
            agg2_kernel<<<ablocks, 256, 0, SA>>>((float4*)dst,
                (const float4*)hw(0), (const float4*)hw(1), rp(0), cvp(0), rp(1), cvp(1), N);
            cudaEventRecord(px.eA01[l], SA);
            cudaStreamWaitEvent(SA, px.eG23[l], 0);
            agg2_kernel<<<ablocks, 256, 0, SA>>>((float4*)(dst + half),
                (const float4*)hw(2), (const float4*)hw(3), rp(2), cvp(2), rp(3), cvp(3), N);
            cudaEventRecord(px.eA23[l], SA);
        } else {
            // layer 5: fused agg + final concat per node class
            agg2_final_kernel<<<ablocks, 256, 0, SA>>>(out,
                (const float4*)A1, (const float4*)AE1,
                (const float4*)hw(0), (const float4*)hw(1),
                rp(0), cvp(0), rp(1), cvp(1), att, N);
            cudaEventRecord(px.eA01[l], SA);
            cudaStreamWaitEvent(SA, px.eG23[l], 0);
            agg2_final_kernel<<<ablocks, 256, 0, SA>>>(out + (size_t)N * 192,
                (const float4*)(A1 + half), (const float4*)(AE1 + half),
                (const float4*)hw(2), (const float4*)hw(3),
                rp(2), cvp(2), rp(3), cvp(3), att, N);
            cudaEventRecord(px.eA23[l], SA);
        }
    }

    // ---- join back to capture-origin stream ----
    cudaStreamWaitEvent(S0, px.eA23[4], 0);
}

// round 10
// speedup vs baseline: 1.1591x; 1.0440x over previous
#include <cuda_runtime.h>
#include <cstdint>

#define MAXN 100000
#define MAXE 1000000
#define HDIM 64

// ---------------------------------------------------------------------------
// Static device scratch (no allocation allowed)
// ---------------------------------------------------------------------------
__device__ float g_A1 [2 * MAXN * HDIM];   // layer1 pre-act (h1 = relu(A1); residual)
__device__ float g_AE1[2 * MAXN * HDIM];   // layer2 pre-act (e1 = relu(AE1))
__device__ float g_B  [2 * MAXN * HDIM];   // layer3 pre-act
__device__ float g_C  [2 * MAXN * HDIM];   // layer4 pre-act
__device__ float g_HW [4 * MAXN * HDIM];   // 4 GEMM outputs (single set — L2 residency)
__device__ int   g_cnt   [4 * MAXN];
__device__ int   g_rowptr[4 * (MAXN + 1)];
__device__ int   g_rowofs[4 * MAXN];
__device__ int2  g_cv    [4 * MAXE];
__device__ int   g_part  [4 * 512];

// ---------------------------------------------------------------------------
// Packed fp32x2 FMA helpers (PTX fma.rn.f32x2 -> FFMA2; verified exact in R9)
// ---------------------------------------------------------------------------
__device__ __forceinline__ unsigned long long pack2(float x) {
    unsigned long long r;
    asm("mov.b64 %0, {%1, %1};" : "=l"(r) : "f"(x));
    return r;
}
__device__ __forceinline__ void ffma2(unsigned long long& d, unsigned long long a,
                                      unsigned long long b) {
    asm("fma.rn.f32x2 %0, %1, %2, %3;" : "=l"(d) : "l"(a), "l"(b), "l"(d));
}
__device__ __forceinline__ void unpack2(unsigned long long v, float& lo, float& hi) {
    asm("mov.b64 {%0, %1}, %2;" : "=f"(lo), "=f"(hi) : "l"(v));
}

// ---------------------------------------------------------------------------
// SIMT GEMM (FFMA2): out[N,64] = act(h)[N,DIN] @ W[DIN,64]
// 256 threads, tile 128 rows x 64 cols, 8x4 register tile (as 8x2 f32x2).
// ---------------------------------------------------------------------------
template <int DIN, bool RELU>
__global__ __launch_bounds__(256) void gemm_kernel(
    float* __restrict__ out, const float* __restrict__ h,
    const float* __restrict__ W, int N) {
    extern __shared__ float smem[];
    float* Ws = smem;              // [DIN][64]
    float* hs = smem + DIN * 64;   // [128][DIN]

    const int tid  = threadIdx.x;
    const int row0 = blockIdx.x * 128;

    for (int i = tid; i < DIN * 16; i += 256)
        reinterpret_cast<float4*>(Ws)[i] = reinterpret_cast<const float4*>(W)[i];

    const int VPR = DIN / 4;
    for (int i = tid; i < 128 * VPR; i += 256) {
        int r = i / VPR, kc = i % VPR;
        int gr = row0 + r;
        float4 v = make_float4(0.f, 0.f, 0.f, 0.f);
        if (gr < N) v = reinterpret_cast<const float4*>(h)[(size_t)gr * VPR + kc];
        if (RELU) {
            v.x = fmaxf(v.x, 0.f); v.y = fmaxf(v.y, 0.f);
            v.z = fmaxf(v.z, 0.f); v.w = fmaxf(v.w, 0.f);
        }
        reinterpret_cast<float4*>(hs)[r * VPR + kc] = v;
    }
    __syncthreads();

    const int tx = tid & 15;   // col group: cols 4*tx..4*tx+3
    const int ty = tid >> 4;   // row group: rows 8*ty..8*ty+7

    unsigned long long acc[8][2];
#pragma unroll
    for (int i = 0; i < 8; i++) { acc[i][0] = 0ull; acc[i][1] = 0ull; }

#pragma unroll 4
    for (int k = 0; k < DIN; k += 4) {
        unsigned long long b2[4][2];
#pragma unroll
        for (int kk = 0; kk < 4; kk++) {
            double2 bd = *reinterpret_cast<double2*>(&Ws[(k + kk) * 64 + tx * 4]);
            b2[kk][0] = __double_as_longlong(bd.x);
            b2[kk][1] = __double_as_longlong(bd.y);
        }
#pragma unroll
        for (int i = 0; i < 8; i++) {
            float4 a = *reinterpret_cast<float4*>(&hs[(ty * 8 + i) * DIN + k]);
            const float* av = reinterpret_cast<const float*>(&a);
#pragma unroll
            for (int kk = 0; kk < 4; kk++) {
                unsigned long long aa = pack2(av[kk]);
                ffma2(acc[i][0], aa, b2[kk][0]);
                ffma2(acc[i][1], aa, b2[kk][1]);
            }
        }
    }

#pragma unroll
    for (int i = 0; i < 8; i++) {
        int r = row0 + ty * 8 + i;
        if (r < N) {
            float4 v;
            unpack2(acc[i][0], v.x, v.y);
            unpack2(acc[i][1], v.z, v.w);
            reinterpret_cast<float4*>(out + (size_t)r * 64 + tx * 4)[0] = v;
        }
    }
}

// ---------------------------------------------------------------------------
// CSR build kernels
// ---------------------------------------------------------------------------
__global__ void hist_kernel(int* __restrict__ cnt, const int* __restrict__ rows,
                            int E, int N) {
    int i = blockIdx.x * blockDim.x + threadIdx.x;
    if (i >= 4 * E) return;
    int t = i / E;
    atomicAdd(&cnt[t * N + __ldg(rows + i)], 1);
}

__global__ void scan_phase1(const int* __restrict__ cnt, int* __restrict__ part,
                            int N, int nb) {
    int t = blockIdx.y, b = blockIdx.x;
    int i = b * 256 + threadIdx.x;
    int v = (i < N) ? cnt[t * N + i] : 0;
#pragma unroll
    for (int o = 16; o; o >>= 1) v += __shfl_down_sync(0xffffffffu, v, o);
    __shared__ int ws[8];
    if ((threadIdx.x & 31) == 0) ws[threadIdx.x >> 5] = v;
    __syncthreads();
    if (threadIdx.x == 0) {
        int s = 0;
#pragma unroll
        for (int j = 0; j < 8; j++) s += ws[j];
        part[t * nb + b] = s;
    }
}

__global__ void scan_phase2(int* __restrict__ part, int* __restrict__ rowptr,
                            int nb, int N, int E) {
    int t = threadIdx.x;
    if (t >= 4) return;
    int s = 0;
    for (int b = 0; b < nb; b++) {
        int v = part[t * nb + b];
        part[t * nb + b] = s;
        s += v;
    }
    rowptr[t * (N + 1) + N] = E;
}

__global__ void scan_phase3(const int* __restrict__ cnt, const int* __restrict__ part,
                            int* __restrict__ rowptr, int* __restrict__ rowofs,
                            int N, int nb) {
    int t = blockIdx.y, b = blockIdx.x;
    int i = b * 256 + threadIdx.x;
    int v = (i < N) ? cnt[t * N + i] : 0;
    __shared__ int sm[256];
    sm[threadIdx.x] = v;
    __syncthreads();
#pragma unroll
    for (int o = 1; o < 256; o <<= 1) {
        int x = (threadIdx.x >= o) ? sm[threadIdx.x - o] : 0;
        __syncthreads();
        sm[threadIdx.x] += x;
        __syncthreads();
    }
    if (i < N) {
        int excl = sm[threadIdx.x] - v + part[t * nb + b];
        rowptr[t * (N + 1) + i] = excl;
        rowofs[t * N + i] = excl;
    }
}

__global__ void fill_kernel(int2* __restrict__ cv, int* __restrict__ rowofs,
                            const int* __restrict__ rows, const int* __restrict__ cols,
                            const float* __restrict__ vals, int E, int N) {
    int i = blockIdx.x * blockDim.x + threadIdx.x;
    if (i >= 4 * E) return;
    int t = i / E;
    int r = __ldg(rows + i);
    int pos = atomicAdd(&rowofs[t * N + r], 1);
    cv[(size_t)t * E + pos] = make_int2(__ldg(cols + i), __float_as_int(__ldg(vals + i)));
}

// ---------------------------------------------------------------------------
// CSR aggregation, 4-deep gather unroll, 2 independent accumulator chains
// ---------------------------------------------------------------------------
__device__ __forceinline__ void fma4(float4& acc, float v, const float4& x) {
    acc.x = fmaf(v, x.x, acc.x);
    acc.y = fmaf(v, x.y, acc.y);
    acc.z = fmaf(v, x.z, acc.z);
    acc.w = fmaf(v, x.w, acc.w);
}

__device__ __forceinline__ void agg_one(float4& acc0, float4& acc1,
                                        const float4* __restrict__ hw,
                                        const int* __restrict__ rp,
                                        const int2* __restrict__ cv, int r, int c) {
    int b = __ldg(rp + r);
    int e = __ldg(rp + r + 1);
    for (; b + 4 <= e; b += 4) {
        int2 p0 = __ldg(cv + b);
        int2 p1 = __ldg(cv + b + 1);
        int2 p2 = __ldg(cv + b + 2);
        int2 p3 = __ldg(cv + b + 3);
        float4 x0 = __ldg(hw + (size_t)p0.x * 16 + c);
        float4 x1 = __ldg(hw + (size_t)p1.x * 16 + c);
        float4 x2 = __ldg(hw + (size_t)p2.x * 16 + c);
        float4 x3 = __ldg(hw + (size_t)p3.x * 16 + c);
        fma4(acc0, __int_as_float(p0.y), x0);
        fma4(acc1, __int_as_float(p1.y), x1);
        fma4(acc0, __int_as_float(p2.y), x2);
        fma4(acc1, __int_as_float(p3.y), x3);
    }
    for (; b < e; b++) {
        int2 p = __ldg(cv + b);
        float4 x = __ldg(hw + (size_t)p.x * 16 + c);
        fma4(acc0, __int_as_float(p.y), x);
    }
}

__global__ __launch_bounds__(256) void agg2_kernel(
    float4* __restrict__ out,
    const float4* __restrict__ hw0, const float4* __restrict__ hw1,
    const int* __restrict__ rp0, const int2* __restrict__ cv0,
    const int* __restrict__ rp1, const int2* __restrict__ cv1, int N) {
    int gid = blockIdx.x * blockDim.x + threadIdx.x;
    int r = gid >> 4, c = gid & 15;
    if (r >= N) return;
    float4 a0 = make_float4(0.f, 0.f, 0.f, 0.f);
    float4 a1 = make_float4(0.f, 0.f, 0.f, 0.f);
    agg_one(a0, a1, hw0, rp0, cv0, r, c);
    agg_one(a0, a1, hw1, rp1, cv1, r, c);
    out[(size_t)r * 16 + c] = make_float4(a0.x + a1.x, a0.y + a1.y,
                                          a0.z + a1.z, a0.w + a1.w);
}

// Layer-5 agg fused with the final attention-concat epilogue (one node class).
// out row r: [0:64) relu(A1)*a0 | [64:128) relu(AE1)*a1 | [128:192) (p+relu(A1))*a2
__global__ __launch_bounds__(256) void agg2_final_kernel(
    float* __restrict__ out,
    const float4* __restrict__ A1, const float4* __restrict__ AE1,
    const float4* __restrict__ hw0, const float4* __restrict__ hw1,
    const int* __restrict__ rp0, const int2* __restrict__ cv0,
    const int* __restrict__ rp1, const int2* __restrict__ cv1,
    const float* __restrict__ att, int N) {
    int gid = blockIdx.x * blockDim.x + threadIdx.x;
    if (gid >= N * 16) return;
    int r = gid >> 4, c = gid & 15;

    float4 a0v = make_float4(0.f, 0.f, 0.f, 0.f);
    float4 a1v = make_float4(0.f, 0.f, 0.f, 0.f);
    agg_one(a0v, a1v, hw0, rp0, cv0, r, c);
    agg_one(a0v, a1v, hw1, rp1, cv1, r, c);
    float4 p = make_float4(a0v.x + a1v.x, a0v.y + a1v.y, a0v.z + a1v.z, a0v.w + a1v.w);

    float a0 = __ldg(att + 0), a1 = __ldg(att + 1), a2 = __ldg(att + 2);

    float4 x1 = A1[(size_t)r * 16 + c];
    x1.x = fmaxf(x1.x, 0.f); x1.y = fmaxf(x1.y, 0.f);
    x1.z = fmaxf(x1.z, 0.f); x1.w = fmaxf(x1.w, 0.f);

    float4 xe = AE1[(size_t)r * 16 + c];
    xe.x = fmaxf(xe.x, 0.f); xe.y = fmaxf(xe.y, 0.f);
    xe.z = fmaxf(xe.z, 0.f); xe.w = fmaxf(xe.w, 0.f);

    float4 emb = make_float4(p.x + x1.x, p.y + x1.y, p.z + x1.z, p.w + x1.w);

    float* o = out + (size_t)r * 192 + (size_t)c * 4;
    reinterpret_cast<float4*>(o + 0)[0]   = make_float4(x1.x * a0, x1.y * a0, x1.z * a0, x1.w * a0);
    reinterpret_cast<float4*>(o + 64)[0]  = make_float4(xe.x * a1, xe.y * a1, xe.z * a1, xe.w * a1);
    reinterpret_cast<float4*>(o + 128)[0] = make_float4(emb.x * a2, emb.y * a2, emb.z * a2, emb.w * a2);
}

// ---------------------------------------------------------------------------
// Host launcher — R7's proven symmetric fork (S0: t0,t1 chain; S1: t2,t3 chain)
// + CSR on its own stream SC + fused layer-5 final.
// ---------------------------------------------------------------------------
struct PipeCtx {
    cudaStream_t s1, sc;
    cudaEvent_t efork, eCSR;
    cudaEvent_t e0[5];  // S0's A01 done (per layer)
    cudaEvent_t e1[5];  // S1's A23 done (per layer)
    PipeCtx() {
        cudaStreamCreateWithFlags(&s1, cudaStreamNonBlocking);
        cudaStreamCreateWithFlags(&sc, cudaStreamNonBlocking);
        cudaEventCreateWithFlags(&efork, cudaEventDisableTiming);
        cudaEventCreateWithFlags(&eCSR,  cudaEventDisableTiming);
        for (int i = 0; i < 5; i++) {
            cudaEventCreateWithFlags(&e0[i], cudaEventDisableTiming);
            cudaEventCreateWithFlags(&e1[i], cudaEventDisableTiming);
        }
    }
};
static PipeCtx& pipe_ctx() { static PipeCtx c; return c; }

extern "C" void kernel_launch(void* const* d_in, const int* in_sizes, int n_in,
                              void* d_out, int out_size) {
    const float* feat0 = (const float*)d_in[0];
    const float* feat1 = (const float*)d_in[1];
    const int*   rows  = (const int*)  d_in[2];
    const int*   cols  = (const int*)  d_in[3];
    const float* vals  = (const float*)d_in[4];
    const float* Wl[5] = {(const float*)d_in[5], (const float*)d_in[6], (const float*)d_in[7],
                          (const float*)d_in[8], (const float*)d_in[9]};
    const float* att   = (const float*)d_in[10];
    float* out = (float*)d_out;

    const int N = in_sizes[0] / 128;   // 100000
    const int E = in_sizes[2] / 4;     // 1000000

    float *A1, *AE1, *B, *C, *HW;
    int *cnt, *rowptr, *rowofs, *part;
    int2* cv;
    cudaGetSymbolAddress((void**)&A1,     g_A1);
    cudaGetSymbolAddress((void**)&AE1,    g_AE1);
    cudaGetSymbolAddress((void**)&B,      g_B);
    cudaGetSymbolAddress((void**)&C,      g_C);
    cudaGetSymbolAddress((void**)&HW,     g_HW);
    cudaGetSymbolAddress((void**)&cnt,    g_cnt);
    cudaGetSymbolAddress((void**)&rowptr, g_rowptr);
    cudaGetSymbolAddress((void**)&rowofs, g_rowofs);
    cudaGetSymbolAddress((void**)&cv,     g_cv);
    cudaGetSymbolAddress((void**)&part,   g_part);

    const int SMEM64  = (64 * 64 + 128 * 64) * 4;    // 48 KB
    const int SMEM128 = (128 * 64 + 128 * 128) * 4;  // 96 KB
    cudaFuncSetAttribute(gemm_kernel<128, false>, cudaFuncAttributeMaxDynamicSharedMemorySize, SMEM128);
    cudaFuncSetAttribute(gemm_kernel<64, true>,   cudaFuncAttributeMaxDynamicSharedMemorySize, SMEM64);

    PipeCtx& px = pipe_ctx();
    cudaStream_t S0 = 0, S1 = px.s1, SC = px.sc;

    const int gblocks = (N + 127) / 128;
    const int ablocks = (N * 16 + 255) / 256;
    const size_t half = (size_t)N * 64;

    auto rp  = [&](int t) { return rowptr + (size_t)t * (N + 1); };
    auto cvp = [&](int t) { return cv + (size_t)t * E; };
    auto hw  = [&](int t) { return HW + (size_t)t * half; };

    // ---- fork ----
    cudaEventRecord(px.efork, S0);
    cudaStreamWaitEvent(S1, px.efork, 0);
    cudaStreamWaitEvent(SC, px.efork, 0);

    // ---- CSR build on SC (overlaps layer-0 GEMMs on S0/S1) ----
    const int nb = (N + 255) / 256;
    cudaMemsetAsync(cnt, 0, (size_t)4 * N * sizeof(int), SC);
    {
        int blocks = (4 * E + 255) / 256;
        hist_kernel<<<blocks, 256, 0, SC>>>(cnt, rows, E, N);
        scan_phase1<<<dim3(nb, 4), 256, 0, SC>>>(cnt, part, N, nb);
        scan_phase2<<<1, 32, 0, SC>>>(part, rowptr, nb, N, E);
        scan_phase3<<<dim3(nb, 4), 256, 0, SC>>>(cnt, part, rowptr, rowofs, N, nb);
        fill_kernel<<<blocks, 256, 0, SC>>>(cv, rowofs, rows, cols, vals, E, N);
    }
    cudaEventRecord(px.eCSR, SC);

    auto gemm = [&](cudaStream_t s, int l, int t, const float* src, int din) {
        const float* Wt = Wl[l] + (size_t)t * din * 64;
        if (din == 128)
            gemm_kernel<128, false><<<gblocks, 256, SMEM128, s>>>(hw(t), src, Wt, N);
        else
            gemm_kernel<64, true><<<gblocks, 256, SMEM64, s>>>(hw(t), src, Wt, N);
    };

    float* dsts[4] = {A1, AE1, B, C};
    for (int l = 0; l < 5; l++) {
        const float* p0;
        const float* p1;
        int din = (l == 0) ? 128 : 64;
        if (l == 0) { p0 = feat0; p1 = feat1; }
        else        { p0 = dsts[l - 1]; p1 = dsts[l - 1] + half; }

        // ----- S0 chain: G0(p0), [p1 ready] G1(p1), A01, rec e0 -----
        gemm(S0, l, 0, p0, din);
        if (l > 0) cudaStreamWaitEvent(S0, px.e1[l - 1], 0);
        gemm(S0, l, 1, p1, din);
        if (l == 0) cudaStreamWaitEvent(S0, px.eCSR, 0);
        // ----- S1 chain: G3(p1), [p0 ready] G2(p0), A23, rec e1 -----
        gemm(S1, l, 3, p1, din);
        if (l > 0) cudaStreamWaitEvent(S1, px.e0[l - 1], 0);
        gemm(S1, l, 2, p0, din);
        if (l == 0) cudaStreamWaitEvent(S1, px.eCSR, 0);

        if (l < 4) {
            float* dst = dsts[l];
            agg2_kernel<<<ablocks, 256, 0, S0>>>((float4*)dst,
                (const float4*)hw(0), (const float4*)hw(1), rp(0), cvp(0), rp(1), cvp(1), N);
            cudaEventRecord(px.e0[l], S0);
            agg2_kernel<<<ablocks, 256, 0, S1>>>((float4*)(dst + half),
                (const float4*)hw(2), (const float4*)hw(3), rp(2), cvp(2), rp(3), cvp(3), N);
            cudaEventRecord(px.e1[l], S1);
        } else {
            // layer 5: fused agg + final concat per node class
            agg2_final_kernel<<<ablocks, 256, 0, S0>>>(out,
                (const float4*)A1, (const float4*)AE1,
                (const float4*)hw(0), (const float4*)hw(1),
                rp(0), cvp(0), rp(1), cvp(1), att, N);
            cudaEventRecord(px.e0[l], S0);
            agg2_final_kernel<<<ablocks, 256, 0, S1>>>(out + (size_t)N * 192,
                (const float4*)(A1 + half), (const float4*)(AE1 + half),
                (const float4*)hw(2), (const float4*)hw(3),
                rp(2), cvp(2), rp(3), cvp(3), att, N);
            cudaEventRecord(px.e1[l], S1);
        }
    }

    // ---- join back to capture-origin stream ----
    cudaStreamWaitEvent(S0, px.e1[4], 0);
}